// round 2
// baseline (speedup 1.0000x reference)
#include <cuda_runtime.h>

// Shapes are fixed by setup_inputs(): B=4, C=8, D=48, H=128, W=160
#define DD   48
#define HH   128
#define WW   160
#define HW   (HH*WW)      // 20480
#define DHW  (DD*HW)      // 983040

typedef unsigned long long u64;

// Packed dual-FP32 FMA: d = a*b + c on both 32-bit halves. Only reachable via PTX.
__device__ __forceinline__ float2 ffma2(float2 a, float2 b, float2 c) {
    union U { float2 f; u64 u; } A, B, C, Dv;
    A.f = a; B.f = b; C.f = c;
    asm("fma.rn.f32x2 %0, %1, %2, %3;" : "=l"(Dv.u) : "l"(A.u), "l"(B.u), "l"(C.u));
    return Dv.f;
}

// Shared-memory folded-weight layout (float indices):
//   [0,256)    w0' duplicated: [o=16][cc=4] float4 = {w[2cc],w[2cc],w[2cc+1],w[2cc+1]}, w0'[o][c] = w0[o][c]*s0[o]
//   [256,288)  b0' duplicated: 16 x float2 {sh,sh},  sh = b0 - m0*s0
//   [288,544)  w1' duplicated: [o=8][cc=8] float4
//   [544,560)  b1' duplicated: 8 x float2
//   [560,576)  w2  duplicated: [cc=4] float4
//   [576,578)  b2  duplicated
#define SWF_FLOATS 592   // padded to 37 float4

__global__ __launch_bounds__(240, 2) void pixelwise_kernel(
    const float* __restrict__ x,
    const float* __restrict__ w0, const float* __restrict__ g0, const float* __restrict__ b0,
    const float* __restrict__ m0, const float* __restrict__ v0,
    const float* __restrict__ w1, const float* __restrict__ g1, const float* __restrict__ b1,
    const float* __restrict__ m1, const float* __restrict__ v1,
    const float* __restrict__ w2, const float* __restrict__ b2,
    float* __restrict__ out)
{
    __shared__ float swf[SWF_FLOATS];
    __shared__ float sred[6 * WW];

    const int tid = threadIdx.x;

    // ---- Prologue: fold BN into conv weights, duplicate into {w,w} pairs (per block, tiny) ----
    if (tid < 128) {
        int o = tid >> 3, c = tid & 7;
        float s = g0[o] * rsqrtf(v0[o] + 1e-5f);
        float vv = w0[tid] * s;
        swf[o * 16 + 2 * c] = vv; swf[o * 16 + 2 * c + 1] = vv;
    }
    if (tid < 16) {
        float s = g0[tid] * rsqrtf(v0[tid] + 1e-5f);
        float sh = b0[tid] - m0[tid] * s;
        swf[256 + 2 * tid] = sh; swf[256 + 2 * tid + 1] = sh;
    }
    if (tid < 128) {
        int o = tid >> 4, c = tid & 15;
        float s = g1[o] * rsqrtf(v1[o] + 1e-5f);
        float vv = w1[tid] * s;
        swf[288 + o * 32 + 2 * c] = vv; swf[288 + o * 32 + 2 * c + 1] = vv;
    }
    if (tid < 8) {
        float s = g1[tid] * rsqrtf(v1[tid] + 1e-5f);
        float sh = b1[tid] - m1[tid] * s;
        swf[544 + 2 * tid] = sh; swf[544 + 2 * tid + 1] = sh;
        swf[560 + 2 * tid] = w2[tid]; swf[560 + 2 * tid + 1] = w2[tid];
    }
    if (tid == 0) { swf[576] = b2[0]; swf[577] = b2[0]; }
    __syncthreads();

    const float4* w0p = (const float4*)(swf);          // 64 float4
    const float2* b0p = (const float2*)(swf + 256);    // 16 float2
    const float4* w1p = (const float4*)(swf + 288);    // 64 float4
    const float2* b1p = (const float2*)(swf + 544);    // 8  float2
    const float4* w2p = (const float4*)(swf + 560);    // 4  float4
    const float2  bias2 = *(const float2*)(swf + 576);

    // ---- Work mapping: block = one (b,h) row. thread = (wq, dg): 4 consecutive w, 8 d values ----
    const int wq = tid % 40;        // 40 groups of 4 w
    const int dg = tid / 40;        // 6 groups of 8 d
    const int b  = blockIdx.x >> 7;
    const int h  = blockIdx.x & 127;

    const float* p = x + (size_t)b * 8 * DHW + h * WW + wq * 4 + dg * 8 * HW;

    float2 mA = make_float2(-1e30f, -1e30f);
    float2 mB = make_float2(-1e30f, -1e30f);

    #pragma unroll 1
    for (int it = 0; it < 8; ++it, p += HW) {
        // load 8 channels x 4 w-positions
        float2 xA[8], xB[8];
        #pragma unroll
        for (int c = 0; c < 8; ++c) {
            float4 t4 = *(const float4*)(p + c * DHW);
            xA[c] = make_float2(t4.x, t4.y);
            xB[c] = make_float2(t4.z, t4.w);
        }

        // layer 0: 8 -> 16, folded BN, ReLU
        float2 hA[16], hB[16];
        #pragma unroll
        for (int o = 0; o < 16; ++o) {
            float2 bb = b0p[o];
            float2 a = bb, q = bb;
            #pragma unroll
            for (int cc = 0; cc < 4; ++cc) {
                float4 wv = w0p[o * 4 + cc];
                float2 wlo = make_float2(wv.x, wv.y);
                float2 whi = make_float2(wv.z, wv.w);
                a = ffma2(wlo, xA[2 * cc],     a);
                q = ffma2(wlo, xB[2 * cc],     q);
                a = ffma2(whi, xA[2 * cc + 1], a);
                q = ffma2(whi, xB[2 * cc + 1], q);
            }
            a.x = fmaxf(a.x, 0.f); a.y = fmaxf(a.y, 0.f);
            q.x = fmaxf(q.x, 0.f); q.y = fmaxf(q.y, 0.f);
            hA[o] = a; hB[o] = q;
        }

        // layer 1: 16 -> 8, folded BN, ReLU
        float2 oA[8], oB[8];
        #pragma unroll
        for (int o = 0; o < 8; ++o) {
            float2 bb = b1p[o];
            float2 a = bb, q = bb;
            #pragma unroll
            for (int cc = 0; cc < 8; ++cc) {
                float4 wv = w1p[o * 8 + cc];
                float2 wlo = make_float2(wv.x, wv.y);
                float2 whi = make_float2(wv.z, wv.w);
                a = ffma2(wlo, hA[2 * cc],     a);
                q = ffma2(wlo, hB[2 * cc],     q);
                a = ffma2(whi, hA[2 * cc + 1], a);
                q = ffma2(whi, hB[2 * cc + 1], q);
            }
            a.x = fmaxf(a.x, 0.f); a.y = fmaxf(a.y, 0.f);
            q.x = fmaxf(q.x, 0.f); q.y = fmaxf(q.y, 0.f);
            oA[o] = a; oB[o] = q;
        }

        // layer 2: 8 -> 1 (+bias); sigmoid deferred past the max (monotone)
        float2 zA = bias2, zB = bias2;
        #pragma unroll
        for (int cc = 0; cc < 4; ++cc) {
            float4 wv = w2p[cc];
            float2 wlo = make_float2(wv.x, wv.y);
            float2 whi = make_float2(wv.z, wv.w);
            zA = ffma2(wlo, oA[2 * cc],     zA);
            zB = ffma2(wlo, oB[2 * cc],     zB);
            zA = ffma2(whi, oA[2 * cc + 1], zA);
            zB = ffma2(whi, oB[2 * cc + 1], zB);
        }

        mA.x = fmaxf(mA.x, zA.x); mA.y = fmaxf(mA.y, zA.y);
        mB.x = fmaxf(mB.x, zB.x); mB.y = fmaxf(mB.y, zB.y);
    }

    // ---- reduce max over the 6 d-groups, then sigmoid ----
    *(float4*)&sred[dg * WW + wq * 4] = make_float4(mA.x, mA.y, mB.x, mB.y);
    __syncthreads();

    if (tid < WW) {
        float m = sred[tid];
        #pragma unroll
        for (int k = 1; k < 6; ++k) m = fmaxf(m, sred[k * WW + tid]);
        out[(size_t)b * HW + h * WW + tid] = 1.f / (1.f + __expf(-m));
    }
}

extern "C" void kernel_launch(void* const* d_in, const int* in_sizes, int n_in,
                              void* d_out, int out_size) {
    const float* x1 = (const float*)d_in[0];
    const float* w0 = (const float*)d_in[1];
    const float* g0 = (const float*)d_in[2];
    const float* b0 = (const float*)d_in[3];
    const float* m0 = (const float*)d_in[4];
    const float* v0 = (const float*)d_in[5];
    const float* w1 = (const float*)d_in[6];
    const float* g1 = (const float*)d_in[7];
    const float* b1 = (const float*)d_in[8];
    const float* m1 = (const float*)d_in[9];
    const float* v1 = (const float*)d_in[10];
    const float* w2 = (const float*)d_in[11];
    const float* b2 = (const float*)d_in[12];

    pixelwise_kernel<<<4 * 128, 240>>>(x1, w0, g0, b0, m0, v0,
                                       w1, g1, b1, m1, v1, w2, b2,
                                       (float*)d_out);
}

// round 4
// speedup vs baseline: 9.4831x; 9.4831x over previous
#include <cuda_runtime.h>

// Fixed shapes: B=4, C=8, D=48, H=128, W=160
#define DD   48
#define HH   128
#define WW   160
#define HW   (HH*WW)      // 20480
#define DHW  (DD*HW)      // 983040

#define NDG    12         // d-groups
#define DPG    4          // d per group (12*4 = 48)
#define SPAN   1024       // pixels per block (contiguous within one d-slice)
#define NSPAN  (HW/SPAN)  // 20
#define THREADS 256       // 4 pixels per thread
#define STAGE_FLOATS (8*SPAN)     // one stage: 8 channels x 1024 px = 32KB
#define WF 592                    // folded-weight floats (16B-aligned: 592*4=2368)
#define DYN_SMEM ((WF + 2*STAGE_FLOATS)*4)   // 67904 bytes

// partial max scratch: [B][NDG][HW] — fully rewritten every launch
__device__ float g_pm[4 * NDG * HW];

typedef unsigned long long u64;

__device__ __forceinline__ float2 ffma2(float2 a, float2 b, float2 c) {
    union U { float2 f; u64 u; } A, B, C, Dv;
    A.f = a; B.f = b; C.f = c;
    asm("fma.rn.f32x2 %0, %1, %2, %3;" : "=l"(Dv.u) : "l"(A.u), "l"(B.u), "l"(C.u));
    return Dv.f;
}

__device__ __forceinline__ unsigned smem_u32(const void* p) {
    return (unsigned)__cvta_generic_to_shared(p);
}

// Weight layout in dyn smem (float idx), all entries duplicated {w,w}:
//  [0,256)   w0' : [o=16][cc=4] float4 {w[2cc],w[2cc],w[2cc+1],w[2cc+1]},  w0'=w0*s0
//  [256,288) b0' : 16 x float2
//  [288,544) w1' : [o=8][cc=8] float4
//  [544,560) b1' : 8 x float2
//  [560,576) w2  : 4 float4
//  [576,578) b2
__device__ __forceinline__ float2 eval_pair(const float* __restrict__ wf,
                                            const float* __restrict__ sxs, int off) {
    const float4* w0p = (const float4*)(wf);
    const float2* b0p = (const float2*)(wf + 256);
    const float4* w1p = (const float4*)(wf + 288);
    const float2* b1p = (const float2*)(wf + 544);
    const float4* w2p = (const float4*)(wf + 560);
    const float2  bz  = *(const float2*)(wf + 576);

    float2 xv[8];
#pragma unroll
    for (int c = 0; c < 8; ++c)
        xv[c] = *(const float2*)(sxs + c * SPAN + off);

    float2 h[16];
#pragma unroll
    for (int o = 0; o < 16; ++o) {
        float2 a = b0p[o];
#pragma unroll
        for (int cc = 0; cc < 4; ++cc) {
            float4 wv = w0p[o * 4 + cc];
            a = ffma2(make_float2(wv.x, wv.y), xv[2 * cc],     a);
            a = ffma2(make_float2(wv.z, wv.w), xv[2 * cc + 1], a);
        }
        a.x = fmaxf(a.x, 0.f); a.y = fmaxf(a.y, 0.f);
        h[o] = a;
    }

    float2 o8[8];
#pragma unroll
    for (int o = 0; o < 8; ++o) {
        float2 a = b1p[o];
#pragma unroll
        for (int cc = 0; cc < 8; ++cc) {
            float4 wv = w1p[o * 8 + cc];
            a = ffma2(make_float2(wv.x, wv.y), h[2 * cc],     a);
            a = ffma2(make_float2(wv.z, wv.w), h[2 * cc + 1], a);
        }
        a.x = fmaxf(a.x, 0.f); a.y = fmaxf(a.y, 0.f);
        o8[o] = a;
    }

    float2 z = bz;
#pragma unroll
    for (int cc = 0; cc < 4; ++cc) {
        float4 wv = w2p[cc];
        z = ffma2(make_float2(wv.x, wv.y), o8[2 * cc],     z);
        z = ffma2(make_float2(wv.z, wv.w), o8[2 * cc + 1], z);
    }
    return z;
}

// issue 8 channel chunks (16B/thread each) for one d-slice into a stage
__device__ __forceinline__ void issue_stage(unsigned sdst, const float* gp) {
#pragma unroll
    for (int c = 0; c < 8; ++c) {
        asm volatile("cp.async.cg.shared.global [%0], [%1], 16;\n"
                     :: "r"(sdst + c * (SPAN * 4)), "l"(gp + (size_t)c * DHW));
    }
    asm volatile("cp.async.commit_group;\n");
}

__global__ __launch_bounds__(THREADS) void pixelwise_k1(
    const float* __restrict__ x,
    const float* __restrict__ w0, const float* __restrict__ g0, const float* __restrict__ b0,
    const float* __restrict__ m0, const float* __restrict__ v0,
    const float* __restrict__ w1, const float* __restrict__ g1, const float* __restrict__ b1,
    const float* __restrict__ m1, const float* __restrict__ v1,
    const float* __restrict__ w2, const float* __restrict__ b2)
{
    extern __shared__ float dynf[];
    float* wf = dynf;                 // [0, WF)
    float* st0 = dynf + WF;           // stage 0
    float* st1 = dynf + WF + STAGE_FLOATS;

    const int tid = threadIdx.x;
    const int bi  = blockIdx.x;
    const int span = bi % NSPAN;
    const int dg   = (bi / NSPAN) % NDG;
    const int b    = bi / (NSPAN * NDG);

    // gmem base: this thread's 4 pixels of d-slice (dg*DPG) for channel 0
    const float* gp = x + (size_t)b * 8 * DHW + (size_t)(dg * DPG) * HW
                        + span * SPAN + tid * 4;

    // start the first two stage loads before doing the weight fold
    unsigned s0a = smem_u32(st0) + tid * 16;
    unsigned s1a = smem_u32(st1) + tid * 16;
    issue_stage(s0a, gp);
    issue_stage(s1a, gp + HW);

    // ---- fold BN into weights, store duplicated {w,w} pairs ----
    if (tid < 128) {
        int o = tid >> 3, c = tid & 7;
        float s = g0[o] * rsqrtf(v0[o] + 1e-5f);
        float vv = w0[tid] * s;
        wf[o * 16 + 2 * c] = vv; wf[o * 16 + 2 * c + 1] = vv;
    }
    if (tid < 16) {
        float s = g0[tid] * rsqrtf(v0[tid] + 1e-5f);
        float sh = b0[tid] - m0[tid] * s;
        wf[256 + 2 * tid] = sh; wf[256 + 2 * tid + 1] = sh;
    }
    if (tid < 128) {
        int o = tid >> 4, c = tid & 15;
        float s = g1[o] * rsqrtf(v1[o] + 1e-5f);
        float vv = w1[tid] * s;
        wf[288 + o * 32 + 2 * c] = vv; wf[288 + o * 32 + 2 * c + 1] = vv;
    }
    if (tid < 8) {
        float s = g1[tid] * rsqrtf(v1[tid] + 1e-5f);
        float sh = b1[tid] - m1[tid] * s;
        wf[544 + 2 * tid] = sh; wf[544 + 2 * tid + 1] = sh;
        wf[560 + 2 * tid] = w2[tid]; wf[560 + 2 * tid + 1] = w2[tid];
    }
    if (tid == 0) { wf[576] = b2[0]; wf[577] = b2[0]; }
    __syncthreads();

    float2 mA = make_float2(-1e30f, -1e30f);
    float2 mB = make_float2(-1e30f, -1e30f);

#pragma unroll
    for (int it = 0; it < DPG; ++it) {
        if (it == DPG - 1) asm volatile("cp.async.wait_group 0;\n" ::: "memory");
        else               asm volatile("cp.async.wait_group 1;\n" ::: "memory");

        const float* sxs = (it & 1) ? st1 : st0;
        int off = tid * 4;

        float2 zA = eval_pair(wf, sxs, off);
        float2 zB = eval_pair(wf, sxs, off + 2);
        mA.x = fmaxf(mA.x, zA.x); mA.y = fmaxf(mA.y, zA.y);
        mB.x = fmaxf(mB.x, zB.x); mB.y = fmaxf(mB.y, zB.y);

        if (it + 2 < DPG) {
            unsigned sdst = (it & 1) ? s1a : s0a;
            issue_stage(sdst, gp + (size_t)(it + 2) * HW);
        }
    }

    // write partial max (sigmoid deferred; it is monotone)
    float4 r = make_float4(mA.x, mA.y, mB.x, mB.y);
    *(float4*)&g_pm[(size_t)(b * NDG + dg) * HW + span * SPAN + tid * 4] = r;
}

__global__ __launch_bounds__(256) void pixelwise_k2(float* __restrict__ out) {
    int i = blockIdx.x * 256 + threadIdx.x;   // 81920 total
    int b  = i / HW;
    int hw = i - b * HW;
    const float* p = g_pm + (size_t)b * NDG * HW + hw;
    float m = p[0];
#pragma unroll
    for (int k = 1; k < NDG; ++k) m = fmaxf(m, p[(size_t)k * HW]);
    out[i] = 1.f / (1.f + __expf(-m));
}

extern "C" void kernel_launch(void* const* d_in, const int* in_sizes, int n_in,
                              void* d_out, int out_size) {
    const float* x1 = (const float*)d_in[0];
    const float* w0 = (const float*)d_in[1];
    const float* g0 = (const float*)d_in[2];
    const float* b0 = (const float*)d_in[3];
    const float* m0 = (const float*)d_in[4];
    const float* v0 = (const float*)d_in[5];
    const float* w1 = (const float*)d_in[6];
    const float* g1 = (const float*)d_in[7];
    const float* b1 = (const float*)d_in[8];
    const float* m1 = (const float*)d_in[9];
    const float* v1 = (const float*)d_in[10];
    const float* w2 = (const float*)d_in[11];
    const float* b2 = (const float*)d_in[12];

    static int attr_done = 0;
    if (!attr_done) {
        cudaFuncSetAttribute(pixelwise_k1,
                             cudaFuncAttributeMaxDynamicSharedMemorySize, DYN_SMEM);
        attr_done = 1;
    }

    pixelwise_k1<<<4 * NDG * NSPAN, THREADS, DYN_SMEM>>>(
        x1, w0, g0, b0, m0, v0, w1, g1, b1, m1, v1, w2, b2);
    pixelwise_k2<<<(4 * HW) / 256, 256>>>((float*)d_out);
}

// round 5
// speedup vs baseline: 9.6354x; 1.0161x over previous
#include <cuda_runtime.h>

// Fixed shapes: B=4, C=8, D=48, H=128, W=160
#define DD   48
#define HH   128
#define WW   160
#define HW   (HH*WW)      // 20480
#define DHW  (DD*HW)      // 983040

#define NDG    12         // d-groups
#define DPG    4          // d per group (12*4 = 48)
#define SPAN   1024       // pixels per block (contiguous within one d-slice)
#define NSPAN  (HW/SPAN)  // 20
#define THREADS 256       // 4 pixels per thread
#define STAGE_FLOATS (8*SPAN)     // one stage: 8 channels x 1024 px = 32KB
#define WF 592                    // folded-weight floats
#define DYN_SMEM ((WF + 2*STAGE_FLOATS)*4)   // 67904 bytes

// partial max scratch: [B][NDG][HW] — fully rewritten every launch
__device__ float g_pm[4 * NDG * HW];

typedef unsigned long long u64;

__device__ __forceinline__ float2 ffma2(float2 a, float2 b, float2 c) {
    union U { float2 f; u64 u; } A, B, C, Dv;
    A.f = a; B.f = b; C.f = c;
    asm("fma.rn.f32x2 %0, %1, %2, %3;" : "=l"(Dv.u) : "l"(A.u), "l"(B.u), "l"(C.u));
    return Dv.f;
}

__device__ __forceinline__ unsigned smem_u32(const void* p) {
    return (unsigned)__cvta_generic_to_shared(p);
}

// Weight layout in dyn smem (float idx), all entries duplicated {w,w}:
//  [0,256)   w0' : [o=16][cc=4] float4 {w[2cc],w[2cc],w[2cc+1],w[2cc+1]},  w0'=w0*s0
//  [256,288) b0' : 16 x float2
//  [288,544) w1T': TRANSPOSED [cin=16][q=4] float4 {w1[2q][cin],dup,w1[2q+1][cin],dup}
//  [544,560) b1' : 8 x float2
//  [560,576) w2  : 4 float4
//  [576,578) b2

// issue 8 channel chunks (16B/thread each) for one d-slice into a stage
__device__ __forceinline__ void issue_stage(unsigned sdst, const float* gp) {
#pragma unroll
    for (int c = 0; c < 8; ++c) {
        asm volatile("cp.async.cg.shared.global [%0], [%1], 16;\n"
                     :: "r"(sdst + c * (SPAN * 4)), "l"(gp + (size_t)c * DHW));
    }
    asm volatile("cp.async.commit_group;\n");
}

__global__ __launch_bounds__(THREADS) void pixelwise_k1(
    const float* __restrict__ x,
    const float* __restrict__ w0, const float* __restrict__ g0, const float* __restrict__ b0,
    const float* __restrict__ m0, const float* __restrict__ v0,
    const float* __restrict__ w1, const float* __restrict__ g1, const float* __restrict__ b1,
    const float* __restrict__ m1, const float* __restrict__ v1,
    const float* __restrict__ w2, const float* __restrict__ b2)
{
    extern __shared__ float dynf[];
    float* wf = dynf;                 // [0, WF)
    float* st0 = dynf + WF;           // stage 0
    float* st1 = dynf + WF + STAGE_FLOATS;

    const int tid = threadIdx.x;
    const int bi  = blockIdx.x;
    const int span = bi % NSPAN;
    const int dg   = (bi / NSPAN) % NDG;
    const int b    = bi / (NSPAN * NDG);

    const float* gp = x + (size_t)b * 8 * DHW + (size_t)(dg * DPG) * HW
                        + span * SPAN + tid * 4;

    unsigned s0a = smem_u32(st0) + tid * 16;
    unsigned s1a = smem_u32(st1) + tid * 16;
    issue_stage(s0a, gp);
    issue_stage(s1a, gp + HW);

    // ---- fold BN into weights (duplicated {w,w} pairs), w1 stored TRANSPOSED ----
    if (tid < 128) {
        int o = tid >> 3, c = tid & 7;
        float s = g0[o] * rsqrtf(v0[o] + 1e-5f);
        float vv = w0[tid] * s;
        wf[o * 16 + 2 * c] = vv; wf[o * 16 + 2 * c + 1] = vv;
    }
    if (tid < 16) {
        float s = g0[tid] * rsqrtf(v0[tid] + 1e-5f);
        float sh = b0[tid] - m0[tid] * s;
        wf[256 + 2 * tid] = sh; wf[256 + 2 * tid + 1] = sh;
    }
    if (tid < 128) {
        int o = tid >> 4, c = tid & 15;          // w1[o][c], o in [0,8), c in [0,16)
        float s = g1[o] * rsqrtf(v1[o] + 1e-5f);
        float vv = w1[tid] * s;
        wf[288 + c * 16 + 2 * o] = vv;           // transposed: [c][o] dup
        wf[288 + c * 16 + 2 * o + 1] = vv;
    }
    if (tid < 8) {
        float s = g1[tid] * rsqrtf(v1[tid] + 1e-5f);
        float sh = b1[tid] - m1[tid] * s;
        wf[544 + 2 * tid] = sh; wf[544 + 2 * tid + 1] = sh;
        wf[560 + 2 * tid] = w2[tid]; wf[560 + 2 * tid + 1] = w2[tid];
    }
    if (tid == 0) { wf[576] = b2[0]; wf[577] = b2[0]; }
    __syncthreads();

    const float4* w0p  = (const float4*)(wf);
    const float2* b0p  = (const float2*)(wf + 256);
    const float4* w1tp = (const float4*)(wf + 288);
    const float2* b1p  = (const float2*)(wf + 544);
    const float4* w2p  = (const float4*)(wf + 560);
    const float2  bz   = *(const float2*)(wf + 576);

    float2 mA = make_float2(-1e30f, -1e30f);
    float2 mB = make_float2(-1e30f, -1e30f);

#pragma unroll
    for (int it = 0; it < DPG; ++it) {
        if (it == DPG - 1) asm volatile("cp.async.wait_group 0;\n" ::: "memory");
        else               asm volatile("cp.async.wait_group 1;\n" ::: "memory");

        const float* sxs = (it & 1) ? st1 : st0;

        // load 8 channels, both pairs at once (LDS.128): .xy = pairA, .zw = pairB
        float4 xq[8];
#pragma unroll
        for (int c = 0; c < 8; ++c)
            xq[c] = *(const float4*)(sxs + c * SPAN + tid * 4);

        // layer-1 accumulators, initialized with folded bias
        float2 aA[8], aB[8];
#pragma unroll
        for (int o = 0; o < 8; ++o) { aA[o] = b1p[o]; aB[o] = b1p[o]; }

        // interleaved layer0 -> layer1: per hidden unit o, compute h then scatter
#pragma unroll
        for (int o = 0; o < 16; ++o) {
            float2 bb = b0p[o];
            float2 hA = bb, hB = bb;
#pragma unroll
            for (int cc = 0; cc < 4; ++cc) {
                float4 wv = w0p[o * 4 + cc];
                float2 wlo = make_float2(wv.x, wv.y);
                float2 whi = make_float2(wv.z, wv.w);
                hA = ffma2(wlo, make_float2(xq[2*cc].x,   xq[2*cc].y),   hA);
                hB = ffma2(wlo, make_float2(xq[2*cc].z,   xq[2*cc].w),   hB);
                hA = ffma2(whi, make_float2(xq[2*cc+1].x, xq[2*cc+1].y), hA);
                hB = ffma2(whi, make_float2(xq[2*cc+1].z, xq[2*cc+1].w), hB);
            }
            hA.x = fmaxf(hA.x, 0.f); hA.y = fmaxf(hA.y, 0.f);
            hB.x = fmaxf(hB.x, 0.f); hB.y = fmaxf(hB.y, 0.f);
#pragma unroll
            for (int q = 0; q < 4; ++q) {
                float4 wv = w1tp[o * 4 + q];
                float2 wlo = make_float2(wv.x, wv.y);
                float2 whi = make_float2(wv.z, wv.w);
                aA[2*q]   = ffma2(wlo, hA, aA[2*q]);
                aB[2*q]   = ffma2(wlo, hB, aB[2*q]);
                aA[2*q+1] = ffma2(whi, hA, aA[2*q+1]);
                aB[2*q+1] = ffma2(whi, hB, aB[2*q+1]);
            }
        }

        // layer2: ReLU then 8->1 dot (+bias); sigmoid deferred (monotone)
        float2 zA = bz, zB = bz;
#pragma unroll
        for (int q = 0; q < 4; ++q) {
            float4 wv = w2p[q];
            float2 wlo = make_float2(wv.x, wv.y);
            float2 whi = make_float2(wv.z, wv.w);
            float2 r0A = make_float2(fmaxf(aA[2*q].x, 0.f),   fmaxf(aA[2*q].y, 0.f));
            float2 r0B = make_float2(fmaxf(aB[2*q].x, 0.f),   fmaxf(aB[2*q].y, 0.f));
            float2 r1A = make_float2(fmaxf(aA[2*q+1].x, 0.f), fmaxf(aA[2*q+1].y, 0.f));
            float2 r1B = make_float2(fmaxf(aB[2*q+1].x, 0.f), fmaxf(aB[2*q+1].y, 0.f));
            zA = ffma2(wlo, r0A, zA);
            zB = ffma2(wlo, r0B, zB);
            zA = ffma2(whi, r1A, zA);
            zB = ffma2(whi, r1B, zB);
        }

        mA.x = fmaxf(mA.x, zA.x); mA.y = fmaxf(mA.y, zA.y);
        mB.x = fmaxf(mB.x, zB.x); mB.y = fmaxf(mB.y, zB.y);

        if (it + 2 < DPG) {
            unsigned sdst = (it & 1) ? s1a : s0a;
            issue_stage(sdst, gp + (size_t)(it + 2) * HW);
        }
    }

    float4 r = make_float4(mA.x, mA.y, mB.x, mB.y);
    *(float4*)&g_pm[(size_t)(b * NDG + dg) * HW + span * SPAN + tid * 4] = r;
}

// reduce 12 partials (float4 per thread, MLP=12), sigmoid, write
__global__ __launch_bounds__(128) void pixelwise_k2(float* __restrict__ out) {
    int t = blockIdx.x * 128 + threadIdx.x;    // 20480 threads
    int b   = t / (HW / 4);
    int hw4 = t - b * (HW / 4);
    const float4* p = (const float4*)g_pm + (size_t)b * NDG * (HW / 4) + hw4;
    float4 m = p[0];
#pragma unroll
    for (int k = 1; k < NDG; ++k) {
        float4 v = p[(size_t)k * (HW / 4)];
        m.x = fmaxf(m.x, v.x); m.y = fmaxf(m.y, v.y);
        m.z = fmaxf(m.z, v.z); m.w = fmaxf(m.w, v.w);
    }
    float4 r;
    r.x = 1.f / (1.f + __expf(-m.x));
    r.y = 1.f / (1.f + __expf(-m.y));
    r.z = 1.f / (1.f + __expf(-m.z));
    r.w = 1.f / (1.f + __expf(-m.w));
    ((float4*)out)[t] = r;
}

extern "C" void kernel_launch(void* const* d_in, const int* in_sizes, int n_in,
                              void* d_out, int out_size) {
    const float* x1 = (const float*)d_in[0];
    const float* w0 = (const float*)d_in[1];
    const float* g0 = (const float*)d_in[2];
    const float* b0 = (const float*)d_in[3];
    const float* m0 = (const float*)d_in[4];
    const float* v0 = (const float*)d_in[5];
    const float* w1 = (const float*)d_in[6];
    const float* g1 = (const float*)d_in[7];
    const float* b1 = (const float*)d_in[8];
    const float* m1 = (const float*)d_in[9];
    const float* v1 = (const float*)d_in[10];
    const float* w2 = (const float*)d_in[11];
    const float* b2 = (const float*)d_in[12];

    static int attr_done = 0;
    if (!attr_done) {
        cudaFuncSetAttribute(pixelwise_k1,
                             cudaFuncAttributeMaxDynamicSharedMemorySize, DYN_SMEM);
        attr_done = 1;
    }

    pixelwise_k1<<<4 * NDG * NSPAN, THREADS, DYN_SMEM>>>(
        x1, w0, g0, b0, m0, v0, w1, g1, b1, m1, v1, w2, b2);
    pixelwise_k2<<<(4 * HW / 4) / 128, 128>>>((float*)d_out);
}